// round 1
// baseline (speedup 1.0000x reference)
#include <cuda_runtime.h>
#include <math.h>

#define NN 384
#define RR 128
#define KK 4
#define JJ 512   // K*R
#define GG 5
#define OO 2

#define PI_OFF  0
#define MU_OFF  (NN*GG)            // 1920
#define SIG_OFF (MU_OFF + NN*GG*OO)  // 5760
#define H_OFF   (SIG_OFF + NN*GG*OO) // 9600
#define C_OFF   (H_OFF + NN*RR)      // 58752

// Scratch (no allocations allowed)
__device__ float g_P[NN*JJ];     // P[m][j] = dot(W_loc[j], nodes[m])
__device__ float g_X[NN*RR];     // x = relu(nodes[:,:4]@W_in^T + b_in) + social
__device__ float g_Wmsum[KK];    // sum_r W_mode[r,k]
__device__ float g_bmsum[1];     // sum_r b_mode[r]

// ---------------------------------------------------------------------------
// K1: P[m][j] = dot6(W_loc[j], nodes[m]); block 0 also reduces W_mode/b_mode.
// ---------------------------------------------------------------------------
__global__ void __launch_bounds__(512) k_pre(
    const float* __restrict__ nodes, const float* __restrict__ W_loc,
    const float* __restrict__ W_mode, const float* __restrict__ b_mode)
{
    int m = blockIdx.x;
    int j = threadIdx.x;
    __shared__ float nd[6];
    if (j < 6) nd[j] = nodes[m*6 + j];
    __syncthreads();
    const float* w = W_loc + j*6;
    g_P[m*JJ + j] = w[0]*nd[0] + w[1]*nd[1] + w[2]*nd[2]
                  + w[3]*nd[3] + w[4]*nd[4] + w[5]*nd[5];

    if (m == 0 && j < 32) {
        float sk0=0.f, sk1=0.f, sk2=0.f, sk3=0.f, sbm=0.f;
        for (int r = j; r < RR; r += 32) {
            sk0 += W_mode[r*4+0];
            sk1 += W_mode[r*4+1];
            sk2 += W_mode[r*4+2];
            sk3 += W_mode[r*4+3];
            sbm += b_mode[r];
        }
        #pragma unroll
        for (int o = 16; o > 0; o >>= 1) {
            sk0 += __shfl_down_sync(0xffffffffu, sk0, o);
            sk1 += __shfl_down_sync(0xffffffffu, sk1, o);
            sk2 += __shfl_down_sync(0xffffffffu, sk2, o);
            sk3 += __shfl_down_sync(0xffffffffu, sk3, o);
            sbm += __shfl_down_sync(0xffffffffu, sbm, o);
        }
        if (j == 0) {
            g_Wmsum[0] = sk0; g_Wmsum[1] = sk1;
            g_Wmsum[2] = sk2; g_Wmsum[3] = sk3;
            g_bmsum[0] = sbm;
        }
    }
}

// ---------------------------------------------------------------------------
// K2: social attention, one block per node n.
// ---------------------------------------------------------------------------
__global__ void __launch_bounds__(256) k_social(
    const float* __restrict__ nodes, const int* __restrict__ visible,
    const float* __restrict__ h_in,  const float* __restrict__ b_loc,
    const float* __restrict__ W_score, const float* __restrict__ b_score,
    const float* __restrict__ W_mode,  const float* __restrict__ b_mode,
    const float* __restrict__ W_in,    const float* __restrict__ b_in)
{
    int n = blockIdx.x;
    int t = threadIdx.x;
    int lane = t & 31;
    int wrp  = t >> 5;

    __shared__ __align__(16) float sPn[JJ];
    __shared__ __align__(16) float sb[JJ];
    __shared__ float shs[RR];
    __shared__ float ssv[NN];
    __shared__ float sal[NN];
    __shared__ int   skh[NN];    // -1 => invisible
    __shared__ float scoef[NN];  // w_i * alpha_i
    __shared__ float sred[8*5];
    __shared__ float sm4[KK], sden[KK], sSk[KK];
    __shared__ float sWtot;
    __shared__ float sscal[8];   // [0]=b_score, [1..4]=Wmsum, [5]=bmsum
    __shared__ float snd[6];
    __shared__ float sChalf[RR];

    sPn[t]      = g_P[n*JJ + t];
    sPn[t+256]  = g_P[n*JJ + 256 + t];
    sb[t]       = b_loc[t];
    sb[t+256]   = b_loc[256 + t];
    if (t < RR) shs[t] = h_in[n*RR + t] * W_score[t];
    if (t == 0) sscal[0] = b_score[0];
    if (t < 4)  sscal[1+t] = g_Wmsum[t];
    if (t == 4) sscal[5] = g_bmsum[0];
    if (t < 6)  snd[t] = nodes[n*6 + t];
    __syncthreads();

    // --- Phase A: per pair (n,i): khat, alpha, sv ---
    for (int i = wrp; i < NN; i += 8) {
        const float4* Pi  = (const float4*)(g_P + i*JJ);
        const float4* Pn4 = (const float4*)sPn;
        const float4* B4  = (const float4*)sb;
        float s0=0.f,s1=0.f,s2=0.f,s3=0.f, L0=0.f,L1=0.f,L2=0.f,L3=0.f;
        #pragma unroll
        for (int u = 0; u < 4; u++) {
            int r = lane + 32*u;
            float4 pi4 = Pi[r];
            float4 pn4 = Pn4[r];
            float4 b4  = B4[r];
            float hv = shs[r];
            float l0 = fmaxf(pn4.x - pi4.x + b4.x, 0.f);
            float l1 = fmaxf(pn4.y - pi4.y + b4.y, 0.f);
            float l2 = fmaxf(pn4.z - pi4.z + b4.z, 0.f);
            float l3 = fmaxf(pn4.w - pi4.w + b4.w, 0.f);
            s0 += l0*hv; s1 += l1*hv; s2 += l2*hv; s3 += l3*hv;
            L0 += l0; L1 += l1; L2 += l2; L3 += l3;
        }
        #pragma unroll
        for (int o = 16; o > 0; o >>= 1) {
            s0 += __shfl_down_sync(0xffffffffu, s0, o);
            s1 += __shfl_down_sync(0xffffffffu, s1, o);
            s2 += __shfl_down_sync(0xffffffffu, s2, o);
            s3 += __shfl_down_sync(0xffffffffu, s3, o);
            L0 += __shfl_down_sync(0xffffffffu, L0, o);
            L1 += __shfl_down_sync(0xffffffffu, L1, o);
            L2 += __shfl_down_sync(0xffffffffu, L2, o);
            L3 += __shfl_down_sync(0xffffffffu, L3, o);
        }
        if (lane == 0) {
            float bs = sscal[0];
            s0 += bs; s1 += bs; s2 += bs; s3 += bs;
            int kh = 0; float smx = s0;
            if (s1 > smx) { smx = s1; kh = 1; }
            if (s2 > smx) { smx = s2; kh = 2; }
            if (s3 > smx) { smx = s3; kh = 3; }
            float e0 = __expf(s0 - smx), e1 = __expf(s1 - smx);
            float e2 = __expf(s2 - smx), e3 = __expf(s3 - smx);
            float soft = 1.0f / (e0 + e1 + e2 + e3);   // soft at khat (e_kh == 1)
            float alpha = (1.0f - soft) + soft;        // straight-through value
            float Lh = (kh==0) ? L0 : (kh==1) ? L1 : (kh==2) ? L2 : L3;
            float sv = alpha*Lh + (alpha*sscal[1+kh] + sscal[5]);
            int vis = visible[n*NN + i];
            skh[i] = (vis > 0) ? kh : -1;
            sal[i] = alpha;
            ssv[i] = sv;
        }
    }
    __syncthreads();

    // --- Phase B: per-head masked softmax over neighbors ---
    // pass 1: max per head
    {
        float m0=-3.0e38f, m1=-3.0e38f, m2=-3.0e38f, m3=-3.0e38f;
        for (int i = t; i < NN; i += 256) {
            int kh = skh[i];
            float v = ssv[i];
            if (kh == 0) m0 = fmaxf(m0, v);
            else if (kh == 1) m1 = fmaxf(m1, v);
            else if (kh == 2) m2 = fmaxf(m2, v);
            else if (kh == 3) m3 = fmaxf(m3, v);
        }
        #pragma unroll
        for (int o = 16; o > 0; o >>= 1) {
            m0 = fmaxf(m0, __shfl_xor_sync(0xffffffffu, m0, o));
            m1 = fmaxf(m1, __shfl_xor_sync(0xffffffffu, m1, o));
            m2 = fmaxf(m2, __shfl_xor_sync(0xffffffffu, m2, o));
            m3 = fmaxf(m3, __shfl_xor_sync(0xffffffffu, m3, o));
        }
        if (lane == 0) {
            sred[wrp*4+0]=m0; sred[wrp*4+1]=m1; sred[wrp*4+2]=m2; sred[wrp*4+3]=m3;
        }
        __syncthreads();
        if (t < 4) {
            float m = sred[t];
            for (int ww = 1; ww < 8; ww++) m = fmaxf(m, sred[ww*4+t]);
            sm4[t] = m;
        }
        __syncthreads();
    }
    // pass 2: denom per head
    {
        float d0=0.f, d1=0.f, d2=0.f, d3=0.f;
        for (int i = t; i < NN; i += 256) {
            int kh = skh[i];
            if (kh >= 0) {
                float e = __expf(ssv[i] - sm4[kh]);
                if (kh == 0) d0 += e;
                else if (kh == 1) d1 += e;
                else if (kh == 2) d2 += e;
                else d3 += e;
            }
        }
        #pragma unroll
        for (int o = 16; o > 0; o >>= 1) {
            d0 += __shfl_xor_sync(0xffffffffu, d0, o);
            d1 += __shfl_xor_sync(0xffffffffu, d1, o);
            d2 += __shfl_xor_sync(0xffffffffu, d2, o);
            d3 += __shfl_xor_sync(0xffffffffu, d3, o);
        }
        if (lane == 0) {
            sred[wrp*4+0]=d0; sred[wrp*4+1]=d1; sred[wrp*4+2]=d2; sred[wrp*4+3]=d3;
        }
        __syncthreads();
        if (t < 4) {
            float d = 0.f;
            for (int ww = 0; ww < 8; ww++) d += sred[ww*4+t];
            sden[t] = d;
        }
        __syncthreads();
    }
    // pass 3: coefficients + group sums
    {
        float k0=0.f, k1=0.f, k2=0.f, k3=0.f, wt=0.f;
        for (int i = t; i < NN; i += 256) {
            int kh = skh[i];
            float c = 0.f;
            if (kh >= 0) {
                float wv = __expf(ssv[i] - sm4[kh]) / sden[kh];
                c = wv * sal[i];
                wt += wv;
                if (kh == 0) k0 += c;
                else if (kh == 1) k1 += c;
                else if (kh == 2) k2 += c;
                else k3 += c;
            }
            scoef[i] = c;
        }
        #pragma unroll
        for (int o = 16; o > 0; o >>= 1) {
            k0 += __shfl_xor_sync(0xffffffffu, k0, o);
            k1 += __shfl_xor_sync(0xffffffffu, k1, o);
            k2 += __shfl_xor_sync(0xffffffffu, k2, o);
            k3 += __shfl_xor_sync(0xffffffffu, k3, o);
            wt += __shfl_xor_sync(0xffffffffu, wt, o);
        }
        if (lane == 0) {
            sred[wrp*5+0]=k0; sred[wrp*5+1]=k1; sred[wrp*5+2]=k2;
            sred[wrp*5+3]=k3; sred[wrp*5+4]=wt;
        }
        __syncthreads();
        if (t < 5) {
            float s = 0.f;
            for (int ww = 0; ww < 8; ww++) s += sred[ww*5+t];
            if (t < 4) sSk[t] = s; else sWtot = s;
        }
        __syncthreads();
    }

    // --- Phase C: social[n][r] accumulation + x ---
    {
        int r = t & 127;
        int half = t >> 7;
        float acc = 0.f;
        int i0 = half * 192;
        for (int i = i0; i < i0 + 192; i++) {
            int kh = skh[i];
            float c = scoef[i];
            if (kh >= 0 && c != 0.f) {
                int j = r*4 + kh;
                acc += c * fmaxf(sPn[j] - g_P[i*JJ + j] + sb[j], 0.f);
            }
        }
        if (half == 1) sChalf[r] = acc;
        __syncthreads();
        if (half == 0) {
            acc += sChalf[r];
            float soc = acc
                + sSk[0]*W_mode[r*4+0] + sSk[1]*W_mode[r*4+1]
                + sSk[2]*W_mode[r*4+2] + sSk[3]*W_mode[r*4+3]
                + sWtot * b_mode[r];
            const float* wi = W_in + r*4;
            float xr = fmaxf(wi[0]*snd[0] + wi[1]*snd[1] + wi[2]*snd[2]
                             + wi[3]*snd[3] + b_in[r], 0.f) + soc;
            g_X[n*RR + r] = xr;
        }
    }
}

// ---------------------------------------------------------------------------
// K3: LSTM cell (batched GEMM) + MDN heads. 8 nodes per block.
// ---------------------------------------------------------------------------
__device__ __forceinline__ float sigf(float x) { return 1.f / (1.f + __expf(-x)); }

__global__ void __launch_bounds__(256) k_lstm(
    const float* __restrict__ h_in, const float* __restrict__ c_in,
    const float* __restrict__ W_ih, const float* __restrict__ W_hh,
    const float* __restrict__ b_ih, const float* __restrict__ b_hh,
    const float* __restrict__ W_pi, const float* __restrict__ b_pi,
    const float* __restrict__ W_mu, const float* __restrict__ b_mu,
    const float* __restrict__ W_sig, const float* __restrict__ b_sig,
    float* __restrict__ out)
{
    const int BN = 8;
    int n0 = blockIdx.x * BN;
    int t = threadIdx.x;

    __shared__ float sX[BN][RR];
    __shared__ float sH[BN][RR];
    __shared__ float sG[BN][JJ];
    __shared__ float sLg[BN][25];

    for (int e = t; e < BN*RR; e += 256) {
        int nn = e >> 7, r = e & 127;
        sX[nn][r] = g_X[(n0+nn)*RR + r];
        sH[nn][r] = h_in[(n0+nn)*RR + r];
    }
    __syncthreads();

    // gates: sG[nn][j] = x@W_ih^T + h@W_hh^T + b_ih + b_hh
    #pragma unroll
    for (int jj = 0; jj < 2; jj++) {
        int j = t*2 + jj;
        const float* wih = W_ih + j*RR;
        const float* whh = W_hh + j*RR;
        float acc[BN];
        #pragma unroll
        for (int nn = 0; nn < BN; nn++) acc[nn] = 0.f;
        #pragma unroll 4
        for (int r = 0; r < RR; r++) {
            float a = wih[r], b = whh[r];
            #pragma unroll
            for (int nn = 0; nn < BN; nn++)
                acc[nn] += sX[nn][r]*a + sH[nn][r]*b;
        }
        float bb = b_ih[j] + b_hh[j];
        #pragma unroll
        for (int nn = 0; nn < BN; nn++) sG[nn][j] = acc[nn] + bb;
    }
    __syncthreads();

    // LSTM combine; write h,c; stash new h in sX
    for (int e = t; e < BN*RR; e += 256) {
        int nn = e >> 7, r = e & 127;
        float gi = sG[nn][r];
        float gf = sG[nn][RR + r];
        float gg = sG[nn][2*RR + r];
        float go = sG[nn][3*RR + r];
        float cp = c_in[(n0+nn)*RR + r];
        float c = sigf(gf)*cp + sigf(gi)*tanhf(gg);
        float h = sigf(go)*tanhf(c);
        out[C_OFF + (n0+nn)*RR + r] = c;
        out[H_OFF + (n0+nn)*RR + r] = h;
        sX[nn][r] = h;
    }
    __syncthreads();

    // heads: 25 dot products per node
    if (t < BN*25) {
        int nn = t / 25, q = t % 25;
        const float* wr = (q < 5)  ? (W_pi + q*RR)
                        : (q < 15) ? (W_mu + (q-5)*RR)
                                   : (W_sig + (q-15)*RR);
        float acc = 0.f;
        #pragma unroll 4
        for (int r = 0; r < RR; r++) acc += wr[r] * sX[nn][r];
        sLg[nn][q] = acc;
    }
    __syncthreads();

    if (t < BN) {  // pi softmax
        int nn = t;
        float l[GG];
        float m = -3.0e38f;
        #pragma unroll
        for (int g = 0; g < GG; g++) { l[g] = sLg[nn][g] + b_pi[g]; m = fmaxf(m, l[g]); }
        float s = 0.f;
        #pragma unroll
        for (int g = 0; g < GG; g++) { l[g] = __expf(l[g] - m); s += l[g]; }
        float inv = 1.f / s;
        #pragma unroll
        for (int g = 0; g < GG; g++)
            out[PI_OFF + (n0+nn)*GG + g] = l[g] * inv;
    }
    if (t >= 64 && t < 64 + BN*10) {  // mu
        int idx = t - 64;
        int nn = idx / 10, q = idx % 10;
        out[MU_OFF + (n0+nn)*10 + q] = sLg[nn][5+q] + b_mu[q];
    }
    if (t >= 160 && t < 160 + BN*10) {  // sigma
        int idx = t - 160;
        int nn = idx / 10, q = idx % 10;
        out[SIG_OFF + (n0+nn)*10 + q] = __expf(sLg[nn][15+q] + b_sig[q]);
    }
}

// ---------------------------------------------------------------------------
extern "C" void kernel_launch(void* const* d_in, const int* in_sizes, int n_in,
                              void* d_out, int out_size)
{
    const float* nodes   = (const float*)d_in[0];
    const int*   visible = (const int*)  d_in[1];
    const float* h_in    = (const float*)d_in[2];
    const float* c_in    = (const float*)d_in[3];
    const float* W_loc   = (const float*)d_in[4];
    const float* b_loc   = (const float*)d_in[5];
    const float* W_score = (const float*)d_in[6];
    const float* b_score = (const float*)d_in[7];
    const float* W_mode  = (const float*)d_in[8];
    const float* b_mode  = (const float*)d_in[9];
    const float* W_in    = (const float*)d_in[10];
    const float* b_in    = (const float*)d_in[11];
    const float* W_ih    = (const float*)d_in[12];
    const float* W_hh    = (const float*)d_in[13];
    const float* b_ih    = (const float*)d_in[14];
    const float* b_hh    = (const float*)d_in[15];
    const float* W_pi    = (const float*)d_in[16];
    const float* b_pi    = (const float*)d_in[17];
    const float* W_mu    = (const float*)d_in[18];
    const float* b_mu    = (const float*)d_in[19];
    const float* W_sig   = (const float*)d_in[20];
    const float* b_sig   = (const float*)d_in[21];
    float* out = (float*)d_out;

    k_pre<<<NN, 512>>>(nodes, W_loc, W_mode, b_mode);
    k_social<<<NN, 256>>>(nodes, visible, h_in, b_loc, W_score, b_score,
                          W_mode, b_mode, W_in, b_in);
    k_lstm<<<NN/8, 256>>>(h_in, c_in, W_ih, W_hh, b_ih, b_hh,
                          W_pi, b_pi, W_mu, b_mu, W_sig, b_sig, out);
}